// round 15
// baseline (speedup 1.0000x reference)
#include <cuda_runtime.h>
#include <math.h>
#include <stdint.h>

#define BN 4096
#define DD 512
#define NT 4
#define NC 65
#define TC 69          // NT + NC
#define NS 4165        // TC + BN
#define CFLD 72        // padded cf row stride
#define NSPL 9         // attention splits
#define NJT 33
#define JPT 4

// ---------------- scratch (device globals; no allocations) ----------------
__device__ float g_xm[BN*DD];
__device__ float g_q[BN*DD];
__device__ float g_kall[NS*DD];
__device__ float g_hA[NS*DD];
__device__ float g_hB[NS*DD];
__device__ float g_hw[NS*DD];
__device__ float g_hw2[72*DD];    // layer-1 (h1_tc @ gw2); rows 69..71 stay 0
__device__ float g_tsum[NT*DD];
__device__ float g_csum[NC*DD];
__device__ int   g_cntT[NT];
__device__ int   g_cntC[NC];
__device__ float g_adj[TC*TC];
__device__ float g_cross[NT*NC];
__device__ float g_cf[BN*CFLD];
__device__ float g_l69[BN*TC];
__device__ float g_mp[16*BN];
__device__ float g_zp[16*BN];
__device__ float g_C69[TC*DD];
__device__ float g_bwPad[DD*CFLD];
__device__ float g_wR[4*DD*DD];   // tf32-rounded: 0=wq 1=wk 2=gw1 3=gw2

// ---------------- static stream/event resources ----------------
static cudaStream_t g_s1;
static cudaEvent_t g_eF, g_e0, g_e1, g_e2, g_e4, g_e5, g_e6;
static struct StreamInit {
    StreamInit() {
        cudaStreamCreateWithFlags(&g_s1, cudaStreamNonBlocking);
        cudaEventCreateWithFlags(&g_eF, cudaEventDisableTiming);
        cudaEventCreateWithFlags(&g_e0, cudaEventDisableTiming);
        cudaEventCreateWithFlags(&g_e1, cudaEventDisableTiming);
        cudaEventCreateWithFlags(&g_e2, cudaEventDisableTiming);
        cudaEventCreateWithFlags(&g_e4, cudaEventDisableTiming);
        cudaEventCreateWithFlags(&g_e5, cudaEventDisableTiming);
        cudaEventCreateWithFlags(&g_e6, cudaEventDisableTiming);
    }
} g_si;

// ---------------- tf32 / mma / cp.async helpers ----------------
__device__ __forceinline__ void mma8(float* c, uint32_t a0, uint32_t a1,
                                     uint32_t a2, uint32_t a3,
                                     uint32_t b0, uint32_t b1) {
    asm("mma.sync.aligned.m16n8k8.row.col.f32.tf32.tf32.f32 "
        "{%0,%1,%2,%3},{%4,%5,%6,%7},{%8,%9},{%0,%1,%2,%3};"
        : "+f"(c[0]), "+f"(c[1]), "+f"(c[2]), "+f"(c[3])
        : "r"(a0), "r"(a1), "r"(a2), "r"(a3), "r"(b0), "r"(b1));
}
__device__ __forceinline__ float rtf(float x) {
    uint32_t u;
    asm("cvt.rna.tf32.f32 %0, %1;" : "=r"(u) : "f"(x));
    return __uint_as_float(u);
}
__device__ __forceinline__ void cpa16(uint32_t dst, const float* src, int srcBytes) {
    asm volatile("cp.async.cg.shared.global [%0], [%1], 16, %2;"
                 :: "r"(dst), "l"(src), "r"(srcBytes));
}
#define CPA_COMMIT() asm volatile("cp.async.commit_group;" ::: "memory")
#define CPA_WAIT0()  asm volatile("cp.async.wait_group 0;" ::: "memory")

// ---------------- selectors ----------------
__device__ __forceinline__ const float* selA3(int s) {
    switch (s) {
        case 0: return g_xm;  case 1: return g_hA;  case 2: return g_hB;
        case 3: return g_cf;  case 4: return g_hA + TC*DD;
    }
    return g_xm;
}
__device__ __forceinline__ const float* selB3(int s, const float* Bp) {
    switch (s) { case 1: return g_hw; case 2: return g_bwPad; case 3: return g_hw2; }
    return Bp;
}
__device__ __forceinline__ float* selC3(int s) {
    switch (s) {
        case 0: return g_q;  case 1: return g_kall;  case 2: return g_hw;
        case 3: return g_hB + TC*DD;  case 4: return g_hA + TC*DD;
        case 5: return g_hw2;  case 6: return g_kall + TC*DD;
    }
    return g_q;
}

// ---------------- xm = mean over 7x7 (tf32-rounded); src rows 69.. ---------
__global__ void k_xm(const float* __restrict__ x) {
    __shared__ float buf[4][32*49];
    int w = threadIdx.x >> 5, lane = threadIdx.x & 31;
    int base = (blockIdx.x*4 + w) * 32;
    const float* src = x + (size_t)base*49;
    float* b = buf[w];
    #pragma unroll
    for (int t = 0; t < 49; t++) b[lane + 32*t] = src[lane + 32*t];
    __syncwarp();
    float s = 0.f;
    #pragma unroll
    for (int t = 0; t < 49; t++) s += b[lane*49 + t];
    s = rtf(s * (1.f/49.f));
    int seg = base + lane;
    g_xm[seg] = s;
    g_hA[TC*DD + seg] = s;
}

// ---------------- prep: zeros, pad+round base_w, round all weights ---------
__global__ void k_prep(const float* __restrict__ wq, const float* __restrict__ wk,
                       const float* __restrict__ gw, const float* __restrict__ bw) {
    int i = blockIdx.x*256 + threadIdx.x;
    if (i < DD*DD) {
        g_wR[i]           = rtf(wq[i]);
        g_wR[DD*DD + i]   = rtf(wk[i]);
        g_wR[2*DD*DD + i] = rtf(gw[i]);
        g_wR[3*DD*DD + i] = rtf(gw[DD*DD + i]);
    }
    if (i < NT*DD) g_tsum[i] = 0.f;
    if (i < NC*DD) g_csum[i] = 0.f;
    if (i < NT) g_cntT[i] = 0;
    if (i < NC) g_cntC[i] = 0;
    if (i < TC*DD) g_C69[i] = 0.f;
    if (i < DD*CFLD) {
        int r = i / CFLD, c = i - r*CFLD;
        g_bwPad[i] = (c < NC) ? rtf(bw[r*NC + c]) : 0.f;
    }
}
__global__ void k_count(const int* __restrict__ to, const int* __restrict__ lb) {
    int i = blockIdx.x*256 + threadIdx.x;
    if (i < BN) { atomicAdd(&g_cntT[to[i]], 1); atomicAdd(&g_cntC[lb[i]], 1); }
}
__global__ void k_segsum(const int* __restrict__ to, const int* __restrict__ lb) {
    __shared__ float sT[NT][64];
    __shared__ float sC[NC][64];
    int t = threadIdx.x;
    int cr = t & 63, rr = t >> 6;
    int r0 = blockIdx.y * 64, c0 = blockIdx.x * 64;
    for (int i = t; i < NT*64; i += 256) ((float*)sT)[i] = 0.f;
    for (int i = t; i < NC*64; i += 256) ((float*)sC)[i] = 0.f;
    __syncthreads();
    for (int r = r0 + rr; r < r0 + 64; r += 4) {
        int tt = to[r], cc = lb[r];
        float v = g_xm[r*DD + c0 + cr];
        atomicAdd(&sT[tt][cr], v);
        atomicAdd(&sC[cc][cr], v);
    }
    __syncthreads();
    for (int i = t; i < NT*64; i += 256)
        atomicAdd(&g_tsum[(i>>6)*DD + c0 + (i&63)], ((float*)sT)[i]);
    for (int i = t; i < NC*64; i += 256)
        atomicAdd(&g_csum[(i>>6)*DD + c0 + (i&63)], ((float*)sC)[i]);
}
__global__ void k_t1c1(const float* __restrict__ trep, const float* __restrict__ cpro) {
    int i = blockIdx.x*256 + threadIdx.x;
    if (i >= TC*DD) return;
    int seg = i / DD, d = i % DD;
    float v;
    if (seg < NT) {
        float cnt = fmaxf((float)g_cntT[seg], 1.f);
        v = 0.9f*trep[i] + 0.1f*g_tsum[i]/cnt;
    } else {
        int c = seg - NT;
        float cnt = fmaxf((float)g_cntC[c], 1.f);
        v = 0.9f*cpro[c*DD+d] + 0.1f*g_csum[c*DD+d]/cnt;
    }
    g_hA[i] = rtf(v);
}

// ---------------- graph kernels ----------------
__global__ void k_d2cross() {
    int c = blockIdx.x;
    int w = threadIdx.x >> 5, lane = threadIdx.x & 31;
    __shared__ float sd2[NT];
    const float* t1 = g_hA;
    const float* c1 = g_hA + NT*DD;
    float s = 0.f;
    for (int d = lane; d < DD; d += 32) {
        float df = t1[w*DD+d] - c1[c*DD+d];
        s += df*df;
    }
    #pragma unroll
    for (int o = 16; o; o >>= 1) s += __shfl_xor_sync(0xffffffffu, s, o);
    if (lane == 0) sd2[w] = s;
    __syncthreads();
    if (threadIdx.x == 0) {
        float l[NT], mx = -1e30f;
        for (int t = 0; t < NT; t++) { l[t] = -sd2[t]*(1.f/16.f); mx = fmaxf(mx, l[t]); }
        float Z = 0.f;
        for (int t = 0; t < NT; t++) { l[t] = expf(l[t]-mx); Z += l[t]; }
        for (int t = 0; t < NT; t++) {
            float p = l[t]/Z;
            g_cross[t*NC + c] = p;
            g_adj[t*TC + NT + c] = p;
            g_adj[(NT+c)*TC + t] = p;
        }
    }
}
__global__ void k_tg(const float* __restrict__ tw, const float* __restrict__ tb) {
    int i = blockIdx.x >> 2, j = blockIdx.x & 3;
    int lane = threadIdx.x;
    const float* t1 = g_hA;
    float s = 0.f;
    for (int d = lane; d < DD; d += 32)
        s += fabsf(t1[i*DD+d]-t1[j*DD+d]) * tw[d];
    #pragma unroll
    for (int o = 16; o; o >>= 1) s += __shfl_xor_sync(0xffffffffu, s, o);
    if (lane == 0) {
        float v = 1.f/(1.f+expf(-(s + tb[0])));
        if (i == j) v = 0.f;
        g_adj[i*TC+j] = v;
    }
}
__global__ void k_cg(const float* __restrict__ cw, const float* __restrict__ cb) {
    int i = blockIdx.x;
    int w = threadIdx.x >> 5, lane = threadIdx.x & 31;
    int j = blockIdx.y*4 + w;
    if (j >= NC) return;
    const float* c1 = g_hA + NT*DD;
    float s = 0.f;
    for (int d = lane; d < DD; d += 32)
        s += fabsf(c1[i*DD+d]-c1[j*DD+d]) * cw[d];
    #pragma unroll
    for (int o = 16; o; o >>= 1) s += __shfl_xor_sync(0xffffffffu, s, o);
    if (lane == 0) {
        float v = 1.f/(1.f+expf(-(s + cb[0])));
        if (i == j) v = 0.f;
        g_adj[(NT+i)*TC + NT+j] = v;
    }
}
__global__ void k_ae(float* out) {
    __shared__ float s[NC];
    int c = threadIdx.x;
    float a = 0.f;
    for (int t = 0; t < NT; t++) { float p = g_cross[t*NC+c]; a += p*logf(p); }
    s[c] = a;
    __syncthreads();
    if (c == 0) { float r = 0.f; for (int i = 0; i < NC; i++) r += s[i]; out[0] = r/(float)NC; }
}

// ---------------- tf32 GEMM (128x128 block tile, cp.async, no hot CVT) -----
#define GEMM_SMEM ((2*128*36 + 2*32*136)*4)
#define AS(p,r,c) smp[(p)*4608 + (r)*36 + (c)]
#define BS(p,r,c) smp[9216 + (p)*4352 + (r)*136 + (c)]
__global__ void __launch_bounds__(256, 2) k_gemm3(
        int aSel, int bSel, const float* __restrict__ Bp, int cSel,
        int M, int N, int K, int lda, int ldb, int ldc,
        const float* __restrict__ bias, int relu,
        const float* __restrict__ tcw, const int* __restrict__ to,
        float* yout) {
    extern __shared__ float smp[];
    int by = blockIdx.y;
    const float* A = selA3(aSel);
    const float* B = selB3(bSel, Bp);
    float* C = yout ? yout : selC3(cSel);
    int tid = threadIdx.x;
    int w = tid >> 5, lane = tid & 31, g = lane >> 2, t = lane & 3;
    int wm = (w & 3) * 32, wn = (w >> 2) * 64;
    int m0 = by*128, n0 = blockIdx.x*128;
    uint32_t sb = (uint32_t)__cvta_generic_to_shared(smp);

    auto fillA = [&](int p, int k0) {
        #pragma unroll
        for (int r = 0; r < 4; r++) {
            int idx = tid + 256*r;
            int row = idx >> 3, fc = idx & 7;
            int gm = m0 + row, gk = k0 + fc*4;
            int sz = 16;
            if (gm >= M) sz = 0;
            int rem = (K - gk)*4;
            if (rem < sz) sz = rem < 0 ? 0 : rem;
            const float* src = sz > 0 ? &A[(size_t)gm*lda + gk] : A;
            cpa16(sb + (uint32_t)(p*4608 + row*36 + fc*4)*4u, src, sz);
        }
    };
    auto fillB = [&](int p, int k0) {
        #pragma unroll
        for (int r = 0; r < 4; r++) {
            int idx = tid + 256*r;
            int row = idx >> 5, c4 = (idx & 31)*4;
            int gk = k0 + row, gn = n0 + c4;
            int sz = 16;
            if (gk >= K) sz = 0;
            int rem = (N - gn)*4;
            if (rem < sz) sz = rem < 0 ? 0 : rem;
            const float* src = sz > 0 ? &B[(size_t)gk*ldb + gn] : B;
            cpa16(sb + (uint32_t)(9216 + p*4352 + row*136 + c4)*4u, src, sz);
        }
    };

    float acc[2][8][4] = {};
    int nk = (K + 31) >> 5;
    fillA(0, 0); fillB(0, 0); CPA_COMMIT();
    for (int kc = 0; kc < nk; kc++) {
        CPA_WAIT0();
        __syncthreads();
        if (kc + 1 < nk) { fillA((kc+1)&1, (kc+1)*32); fillB((kc+1)&1, (kc+1)*32); CPA_COMMIT(); }
        int p = kc & 1;
        #pragma unroll
        for (int kk = 0; kk < 32; kk += 8) {
            uint32_t a[2][4];
            #pragma unroll
            for (int mi = 0; mi < 2; mi++) {
                a[mi][0] = __float_as_uint(AS(p, wm+mi*16+g  , kk+t));
                a[mi][1] = __float_as_uint(AS(p, wm+mi*16+g+8, kk+t));
                a[mi][2] = __float_as_uint(AS(p, wm+mi*16+g  , kk+t+4));
                a[mi][3] = __float_as_uint(AS(p, wm+mi*16+g+8, kk+t+4));
            }
            uint32_t b[8][2];
            #pragma unroll
            for (int ni = 0; ni < 8; ni++) {
                b[ni][0] = __float_as_uint(BS(p, kk+t  , wn+ni*8+g));
                b[ni][1] = __float_as_uint(BS(p, kk+t+4, wn+ni*8+g));
            }
            #pragma unroll
            for (int mi = 0; mi < 2; mi++)
                #pragma unroll
                for (int ni = 0; ni < 8; ni++)
                    mma8(acc[mi][ni], a[mi][0], a[mi][1], a[mi][2], a[mi][3],
                         b[ni][0], b[ni][1]);
        }
    }
    #pragma unroll
    for (int mi = 0; mi < 2; mi++) {
        int r0 = m0 + wm + mi*16 + g, r1 = r0 + 8;
        #pragma unroll
        for (int ni = 0; ni < 8; ni++) {
            int n = n0 + wn + ni*8 + 2*t;
            float bv0 = 0.f, bv1 = 0.f;
            if (bias) { if (n < N) bv0 = bias[n]; if (n+1 < N) bv1 = bias[n+1]; }
            float v00 = acc[mi][ni][0] + bv0, v01 = acc[mi][ni][1] + bv1;
            float v10 = acc[mi][ni][2] + bv0, v11 = acc[mi][ni][3] + bv1;
            if (relu) {
                v00 = fmaxf(v00, 0.f); v01 = fmaxf(v01, 0.f);
                v10 = fmaxf(v10, 0.f); v11 = fmaxf(v11, 0.f);
            }
            if (yout) {
                if (r0 < M) {
                    if (n < N)   C[(size_t)r0*ldc + n]   = tcw[to[r0]*NC + n]   * v00;
                    if (n+1 < N) C[(size_t)r0*ldc + n+1] = tcw[to[r0]*NC + n+1] * v01;
                }
                if (r1 < M) {
                    if (n < N)   C[(size_t)r1*ldc + n]   = tcw[to[r1]*NC + n]   * v10;
                    if (n+1 < N) C[(size_t)r1*ldc + n+1] = tcw[to[r1]*NC + n+1] * v11;
                }
            } else {
                v00 = rtf(v00); v01 = rtf(v01); v10 = rtf(v10); v11 = rtf(v11);
                if (r0 < M) {
                    if (n < N)   C[(size_t)r0*ldc + n]   = v00;
                    if (n+1 < N) C[(size_t)r0*ldc + n+1] = v01;
                }
                if (r1 < M) {
                    if (n < N)   C[(size_t)r1*ldc + n]   = v10;
                    if (n+1 < N) C[(size_t)r1*ldc + n+1] = v11;
                }
            }
        }
    }
}

// ---------------- attention (cp.async, streaming softmax, raw loads) -------
// split = blockIdx.y + splitBase; splits 1.. touch only x-keys (>=128).
#define ATTN_SMEM ((2*128*36*2)*4)
#define QS(p,r,c) smp[(p)*4608 + (r)*36 + (c)]
#define KS(p,r,c) smp[9216 + (p)*4608 + (r)*36 + (c)]
__global__ void __launch_bounds__(256, 2) k_attn3(int splitBase) {
    extern __shared__ float smp[];
    __shared__ float sm_m[2][128];
    __shared__ float sm_z[2][128];
    int tid = threadIdx.x;
    int w = tid >> 5, lane = tid & 31, g = lane >> 2, t = lane & 3;
    int wm = (w & 3) * 32, wn = (w >> 2) * 64;
    int half = w >> 2;
    int i0 = blockIdx.x*128;
    int split = blockIdx.y + splitBase;
    const float sc = 0.044194173824159216f;   // 1/sqrt(512)
    uint32_t sb = (uint32_t)__cvta_generic_to_shared(smp);

    auto fillQ = [&](int p, int k0) {
        #pragma unroll
        for (int r = 0; r < 4; r++) {
            int idx = tid + 256*r;
            int row = idx >> 3, fc = idx & 7;
            cpa16(sb + (uint32_t)(p*4608 + row*36 + fc*4)*4u,
                  &g_q[(size_t)(i0+row)*DD + k0 + fc*4], 16);
        }
    };
    auto fillK = [&](int p, int j0v, int k0) {
        #pragma unroll
        for (int r = 0; r < 4; r++) {
            int idx = tid + 256*r;
            int row = idx >> 3, fc = idx & 7;
            int gj = j0v + row;
            int sz = gj < NS ? 16 : 0;
            const float* src = sz ? &g_kall[(size_t)gj*DD + k0 + fc*4] : g_kall;
            cpa16(sb + (uint32_t)(9216 + p*4608 + row*36 + fc*4)*4u, src, sz);
        }
    };

    float mr[2][2] = {{-1e30f,-1e30f},{-1e30f,-1e30f}};
    float zr[2][2] = {{0.f,0.f},{0.f,0.f}};
    int jt0 = split*JPT;
    int jt1 = jt0 + JPT; if (jt1 > NJT) jt1 = NJT;
    int cg = 0;
    fillQ(0, 0); fillK(0, jt0*128, 0); CPA_COMMIT();
    for (int jt = jt0; jt < jt1; jt++) {
        int j0 = jt*128;
        float acc[2][8][4] = {};
        for (int c = 0; c < 16; c++, cg++) {
            CPA_WAIT0();
            __syncthreads();
            int p = cg & 1;
            if (c < 15) {
                fillQ(p^1, (c+1)*32); fillK(p^1, j0, (c+1)*32); CPA_COMMIT();
            } else if (jt + 1 < jt1) {
                fillQ(p^1, 0); fillK(p^1, (jt+1)*128, 0); CPA_COMMIT();
            }
            #pragma unroll
            for (int kk = 0; kk < 32; kk += 8) {
                uint32_t a[2][4];
                #pragma unroll
                for (int mi = 0; mi < 2; mi++) {
                    a[mi][0] = __float_as_uint(QS(p, wm+mi*16+g  , kk+t));
                    a[mi][1] = __float_as_uint(QS(p, wm+mi*16+g+8, kk+t));
                    a[mi][2] = __float_as_uint(QS(p, wm+mi*16+g  , kk+t+4));
                    a[mi][3] = __float_as_uint(QS(p, wm+mi*16+g+8, kk+t+4));
                }
                uint32_t b[8][2];
                #pragma unroll
                for (int ni = 0; ni < 8; ni++) {
                    b[ni][0] = __float_as_uint(KS(p, wn+ni*8+g, kk+t));
                    b[ni][1] = __float_as_uint(KS(p, wn+ni*8+g, kk+t+4));
                }
                #pragma unroll
                for (int mi = 0; mi < 2; mi++)
                    #pragma unroll
                    for (int ni = 0; ni < 8; ni++)
                        mma8(acc[mi][ni], a[mi][0], a[mi][1], a[mi][2], a[mi][3],
                             b[ni][0], b[ni][1]);
            }
        }
        int doL = (split == 0 && jt == 0);
        #pragma unroll
        for (int mi = 0; mi < 2; mi++) {
            int r0g = i0 + wm + mi*16 + g, r1g = r0g + 8;
            float lm0 = -1e30f, lm1 = -1e30f;
            #pragma unroll
            for (int ni = 0; ni < 8; ni++) {
                int base = j0 + wn + ni*8 + 2*t;
                float v0 = (base   < NS) ? acc[mi][ni][0]*sc : -1e30f;
                float v1 = (base+1 < NS) ? acc[mi][ni][1]*sc : -1e30f;
                float v2 = (base   < NS) ? acc[mi][ni][2]*sc : -1e30f;
                float v3 = (base+1 < NS) ? acc[mi][ni][3]*sc : -1e30f;
                acc[mi][ni][0] = v0; acc[mi][ni][1] = v1;
                acc[mi][ni][2] = v2; acc[mi][ni][3] = v3;
                if (doL) {
                    int c0 = wn + ni*8 + 2*t;
                    if (c0 < TC) {
                        g_l69[(size_t)r0g*TC + c0] = v0;
                        g_l69[(size_t)r1g*TC + c0] = v2;
                    }
                    if (c0 + 1 < TC) {
                        g_l69[(size_t)r0g*TC + c0+1] = v1;
                        g_l69[(size_t)r1g*TC + c0+1] = v3;
                    }
                }
                lm0 = fmaxf(lm0, fmaxf(v0, v1));
                lm1 = fmaxf(lm1, fmaxf(v2, v3));
            }
            lm0 = fmaxf(lm0, __shfl_xor_sync(0xffffffffu, lm0, 1));
            lm0 = fmaxf(lm0, __shfl_xor_sync(0xffffffffu, lm0, 2));
            lm1 = fmaxf(lm1, __shfl_xor_sync(0xffffffffu, lm1, 1));
            lm1 = fmaxf(lm1, __shfl_xor_sync(0xffffffffu, lm1, 2));
            float nm0 = fmaxf(mr[mi][0], lm0), nm1 = fmaxf(mr[mi][1], lm1);
            float p0 = 0.f, p1 = 0.f;
            #pragma unroll
            for (int ni = 0; ni < 8; ni++) {
                p0 += __expf(acc[mi][ni][0]-nm0) + __expf(acc[mi][ni][1]-nm0);
                p1 += __expf(acc[mi][ni][2]-nm1) + __expf(acc[mi][ni][3]-nm1);
            }
            p0 += __shfl_xor_sync(0xffffffffu, p0, 1);
            p0 += __shfl_xor_sync(0xffffffffu, p0, 2);
            p1 += __shfl_xor_sync(0xffffffffu, p1, 1);
            p1 += __shfl_xor_sync(0xffffffffu, p1, 2);
            zr[mi][0] = zr[mi][0]*__expf(mr[mi][0] - nm0) + p0; mr[mi][0] = nm0;
            zr[mi][1] = zr[mi][1]*__expf(mr[mi][1] - nm1) + p1; mr[mi][1] = nm1;
        }
    }
    if (t == 0) {
        #pragma unroll
        for (int mi = 0; mi < 2; mi++) {
            int r = wm + mi*16 + g;
            sm_m[half][r]     = mr[mi][0];  sm_z[half][r]     = zr[mi][0];
            sm_m[half][r + 8] = mr[mi][1];  sm_z[half][r + 8] = zr[mi][1];
        }
    }
    __syncthreads();
    if (tid < 128) {
        float m0 = sm_m[0][tid], m1 = sm_m[1][tid];
        float m = fmaxf(m0, m1);
        float z = sm_z[0][tid]*__expf(m0 - m) + sm_z[1][tid]*__expf(m1 - m);
        g_mp[split*BN + i0 + tid] = m;
        g_zp[split*BN + i0 + tid] = z;
    }
}

// ---------------- combine splits + first-69 softmax -> cf (tf32) ----------
__global__ void k_cf() {
    int i = blockIdx.x;
    int j = threadIdx.x;
    __shared__ float sh[2];
    if (j == 0) {
        float m = -1e30f;
        #pragma unroll
        for (int s = 0; s < NSPL; s++) m = fmaxf(m, g_mp[s*BN + i]);
        float z = 0.f;
        #pragma unroll
        for (int s = 0; s < NSPL; s++) z += g_zp[s*BN + i]*__expf(g_mp[s*BN + i] - m);
        sh[0] = m; sh[1] = 1.f/z;
    }
    __syncthreads();
    if (j < CFLD)
        g_cf[i*CFLD + j] = (j < TC) ? rtf(__expf(g_l69[i*TC + j] - sh[0]) * sh[1]) : 0.f;
}

// ---------------- GNN tc-rows partial: C69 += cf^T @ hw_x ----------------
__global__ void k_outtc() {
    __shared__ float cfs[64][72];
    __shared__ float hws[64][64];
    int t = threadIdx.x, tx = t & 63, ty = t >> 6;
    int n0 = blockIdx.x*64;
    int b0 = blockIdx.y*256;
    float acc[18];
    #pragma unroll
    for (int k = 0; k < 18; k++) acc[k] = 0.f;
    for (int bc = 0; bc < 256; bc += 64) {
        int bb = b0 + bc;
        for (int i = t; i < 64*TC; i += 256) {
            int r = i/TC, k = i%TC;
            cfs[r][k] = g_cf[(size_t)(bb+r)*CFLD + k];
        }
        for (int i = t; i < 64*64; i += 256) {
            int r = i >> 6, n = i & 63;
            hws[r][n] = g_hw[(size_t)(TC+bb+r)*DD + n0 + n];
        }
        __syncthreads();
        for (int r = 0; r < 64; r++) {
            float hv = hws[r][tx];
            #pragma unroll
            for (int k = 0; k < 18; k++) {
                int m = ty + 4*k;
                if (m < TC) acc[k] += cfs[r][m]*hv;
            }
        }
        __syncthreads();
    }
    #pragma unroll
    for (int k = 0; k < 18; k++) {
        int m = ty + 4*k;
        if (m < TC) atomicAdd(&g_C69[m*DD + n0 + tx], acc[k]);
    }
}

// ---------------- finalize tc rows (layer 0), tf32-rounded ------------
__global__ void k_fintc(const float* __restrict__ gb) {
    int m = blockIdx.x;      // 69
    int n = threadIdx.x;     // 512
    float v = g_C69[m*DD + n];
    for (int j = 0; j < TC; j++)
        v += g_adj[m*TC+j] * g_hw[j*DD + n];
    v += gb[n];
    g_hB[m*DD + n] = rtf(fmaxf(v, 0.f));
}

// ---------------- labels ----------------
__global__ void k_labels(const int* __restrict__ lb, float* out, int off, int out_size) {
    int i = blockIdx.x*256 + threadIdx.x;
    if (i < BN && off + i < out_size) out[off + i] = (float)lb[i];
}

// ======================== host ========================
extern "C" void kernel_launch(void* const* d_in, const int* in_sizes, int n_in,
                              void* d_out, int out_size) {
    const float* x    = (const float*)d_in[0];
    const int*   lb   = (const int*)d_in[1];
    const int*   to   = (const int*)d_in[2];
    const float* trep = (const float*)d_in[3];
    const float* cpro = (const float*)d_in[4];
    const float* tw   = (const float*)d_in[5];
    const float* tb   = (const float*)d_in[6];
    const float* cw   = (const float*)d_in[7];
    const float* cb   = (const float*)d_in[8];
    const float* wq   = (const float*)d_in[9];
    const float* wk   = (const float*)d_in[10];
    const float* gw   = (const float*)d_in[11];
    const float* gb   = (const float*)d_in[12];
    const float* bw   = (const float*)d_in[13];
    const float* bb   = (const float*)d_in[14];
    const float* tcw  = (const float*)d_in[15];
    float* out = (float*)d_out;

    cudaFuncSetAttribute(k_gemm3, cudaFuncAttributeMaxDynamicSharedMemorySize, GEMM_SMEM);
    cudaFuncSetAttribute(k_attn3, cudaFuncAttributeMaxDynamicSharedMemorySize, ATTN_SMEM);

    float* wRp = nullptr;
    cudaGetSymbolAddress((void**)&wRp, g_wR);
    const float* wqR  = wRp;
    const float* wkR  = wRp + DD*DD;
    const float* gw1R = wRp + 2*DD*DD;
    const float* gw2R = wRp + 3*DD*DD;

    int y_off = (out_size > BN*NC) ? 1 : 0;
    int lbl_off = y_off + BN*NC;

    // FORK (capture-legal side-stream entry)
    cudaEventRecord(g_eF, 0);
    cudaStreamWaitEvent(g_s1, g_eF, 0);
    // side: prep + count, concurrent with xm
    k_prep<<<(DD*DD + 255)/256, 256, 0, g_s1>>>(wq, wk, gw, bw);
    k_count<<<16, 256, 0, g_s1>>>(to, lb);
    cudaEventRecord(g_e0, g_s1);
    // main: xm
    k_xm<<<16384, 128>>>(x);
    cudaEventRecord(g_e1, 0);
    // side: q = xm@wqR, concurrent with kall_x on main
    cudaStreamWaitEvent(g_s1, g_e1, 0);
    k_gemm3<<<dim3(4, 32), 256, GEMM_SMEM, g_s1>>>(0, 0, wqR, 0, BN, DD, DD, DD, DD, DD,
                                                   nullptr, 0, nullptr, nullptr, nullptr);
    cudaEventRecord(g_e4, g_s1);
    // main: kall_x = xm@wkR -> g_kall rows 69.. (needs xm + prep)
    cudaStreamWaitEvent(0, g_e0, 0);
    k_gemm3<<<dim3(4, 32), 256, GEMM_SMEM>>>(0, 0, wkR, 6, BN, DD, DD, DD, DD, DD,
                                             nullptr, 0, nullptr, nullptr, nullptr);
    // main: attention splits 1..8 (x-keys only; needs q + kall_x)
    cudaStreamWaitEvent(0, g_e4, 0);
    k_attn3<<<dim3(32, 8), 256, ATTN_SMEM>>>(1);
    // side (concurrent with attnA): segsum -> t1c1 -> kall_tc -> graphs -> hw
    k_segsum<<<dim3(8, 64), 256, 0, g_s1>>>(to, lb);
    k_t1c1<<<(TC*DD + 255)/256, 256, 0, g_s1>>>(trep, cpro);
    k_gemm3<<<dim3(4, 1), 256, GEMM_SMEM, g_s1>>>(1, 0, wkR, 1, TC, DD, DD, DD, DD, DD,
                                                  nullptr, 0, nullptr, nullptr, nullptr);
    cudaEventRecord(g_e5, g_s1);   // kall_tc ready
    k_d2cross<<<65, 128, 0, g_s1>>>();
    k_tg<<<16, 32, 0, g_s1>>>(tw, tb);
    k_cg<<<dim3(65, 17), 128, 0, g_s1>>>(cw, cb);
    if (y_off) k_ae<<<1, 65, 0, g_s1>>>(out);
    k_gemm3<<<dim3(4, 33), 256, GEMM_SMEM, g_s1>>>(1, 0, gw1R, 2, NS, DD, DD, DD, DD, DD,
                                                   nullptr, 0, nullptr, nullptr, nullptr);
    cudaEventRecord(g_e6, g_s1);   // hw + graphs ready
    // main: attention split 0 (needs kall_tc)
    cudaStreamWaitEvent(0, g_e5, 0);
    k_attn3<<<dim3(32, 1), 256, ATTN_SMEM>>>(0);
    k_cf<<<4096, 96>>>();
    // main tail (needs hw + adj): outtc -> fintc -> hw2 -> L1x -> y
    cudaStreamWaitEvent(0, g_e6, 0);
    k_outtc<<<dim3(8, 16), 256>>>();
    k_fintc<<<69, 512>>>(gb);
    k_gemm3<<<dim3(4, 1), 256, GEMM_SMEM>>>(2, 0, gw2R, 5, TC, DD, DD, DD, DD, DD,
                                            nullptr, 0, nullptr, nullptr, nullptr);
    k_gemm3<<<dim3(4, 32), 256, GEMM_SMEM>>>(3, 3, nullptr, 4, BN, DD, CFLD, CFLD, DD, DD,
                                             gb + DD, 1, nullptr, nullptr, nullptr);
    k_gemm3<<<dim3(1, 32), 256, GEMM_SMEM>>>(4, 2, nullptr, 0, BN, NC, DD, DD, CFLD, NC,
                                             bb, 0, tcw, to, out + y_off);
    k_labels<<<16, 256>>>(lb, out, lbl_off, out_size);
}

// round 16
// speedup vs baseline: 1.1432x; 1.1432x over previous
#include <cuda_runtime.h>
#include <math.h>
#include <stdint.h>

#define BN 4096
#define DD 512
#define NT 4
#define NC 65
#define TC 69          // NT + NC
#define NS 4165        // TC + BN
#define CFLD 72        // padded cf row stride
#define NSPL 9         // attention splits (0: jt0 only; 1..8: 4 jt each)
#define NJT 33
#define JPT 4

// ---------------- scratch (device globals; no allocations) ----------------
__device__ float g_xm[BN*DD];
__device__ float g_q[BN*DD];
__device__ float g_kall[NS*DD];
__device__ float g_hA[NS*DD];
__device__ float g_hB[NS*DD];
__device__ float g_hw[NS*DD];
__device__ float g_hw2[72*DD];    // layer-1 (h1_tc @ gw2); rows 69..71 stay 0
__device__ float g_tsum[NT*DD];
__device__ float g_csum[NC*DD];
__device__ int   g_cntT[NT];
__device__ int   g_cntC[NC];
__device__ float g_adj[TC*TC];
__device__ float g_cross[NT*NC];
__device__ float g_cf[BN*CFLD];
__device__ float g_l69[BN*TC];
__device__ float g_mp[16*BN];
__device__ float g_zp[16*BN];
__device__ float g_C69[TC*DD];
__device__ float g_bwPad[DD*CFLD];
__device__ float g_wR[4*DD*DD];   // tf32-rounded: 0=wq 1=wk 2=gw1 3=gw2

// ---------------- static stream/event resources ----------------
static cudaStream_t g_s1;
static cudaEvent_t g_eF, g_e0, g_e1, g_e4, g_e5, g_e6;
static struct StreamInit {
    StreamInit() {
        cudaStreamCreateWithFlags(&g_s1, cudaStreamNonBlocking);
        cudaEventCreateWithFlags(&g_eF, cudaEventDisableTiming);
        cudaEventCreateWithFlags(&g_e0, cudaEventDisableTiming);
        cudaEventCreateWithFlags(&g_e1, cudaEventDisableTiming);
        cudaEventCreateWithFlags(&g_e4, cudaEventDisableTiming);
        cudaEventCreateWithFlags(&g_e5, cudaEventDisableTiming);
        cudaEventCreateWithFlags(&g_e6, cudaEventDisableTiming);
    }
} g_si;

// ---------------- tf32 / mma / cp.async helpers ----------------
__device__ __forceinline__ void mma8(float* c, uint32_t a0, uint32_t a1,
                                     uint32_t a2, uint32_t a3,
                                     uint32_t b0, uint32_t b1) {
    asm("mma.sync.aligned.m16n8k8.row.col.f32.tf32.tf32.f32 "
        "{%0,%1,%2,%3},{%4,%5,%6,%7},{%8,%9},{%0,%1,%2,%3};"
        : "+f"(c[0]), "+f"(c[1]), "+f"(c[2]), "+f"(c[3])
        : "r"(a0), "r"(a1), "r"(a2), "r"(a3), "r"(b0), "r"(b1));
}
__device__ __forceinline__ float rtf(float x) {
    uint32_t u;
    asm("cvt.rna.tf32.f32 %0, %1;" : "=r"(u) : "f"(x));
    return __uint_as_float(u);
}
__device__ __forceinline__ void cpa16(uint32_t dst, const float* src, int srcBytes) {
    asm volatile("cp.async.cg.shared.global [%0], [%1], 16, %2;"
                 :: "r"(dst), "l"(src), "r"(srcBytes));
}
#define CPA_COMMIT() asm volatile("cp.async.commit_group;" ::: "memory")
#define CPA_WAIT0()  asm volatile("cp.async.wait_group 0;" ::: "memory")

// ---------------- selectors ----------------
__device__ __forceinline__ const float* selA3(int s) {
    switch (s) {
        case 0: return g_xm;  case 1: return g_hA;  case 2: return g_hB;
        case 3: return g_cf;  case 4: return g_hA + TC*DD;
    }
    return g_xm;
}
__device__ __forceinline__ const float* selB3(int s, const float* Bp) {
    switch (s) { case 1: return g_hw; case 2: return g_bwPad; case 3: return g_hw2; }
    return Bp;
}
__device__ __forceinline__ float* selC3(int s) {
    switch (s) {
        case 0: return g_q;  case 1: return g_kall;  case 2: return g_hw;
        case 3: return g_hB + TC*DD;  case 4: return g_hA + TC*DD;
        case 5: return g_hw2;  case 6: return g_kall + TC*DD;
    }
    return g_q;
}

// ---------------- xm = mean over 7x7 (tf32-rounded); src rows 69.. ---------
__global__ void k_xm(const float* __restrict__ x) {
    __shared__ float buf[4][32*49];
    int w = threadIdx.x >> 5, lane = threadIdx.x & 31;
    int base = (blockIdx.x*4 + w) * 32;
    const float* src = x + (size_t)base*49;
    float* b = buf[w];
    #pragma unroll
    for (int t = 0; t < 49; t++) b[lane + 32*t] = src[lane + 32*t];
    __syncwarp();
    float s = 0.f;
    #pragma unroll
    for (int t = 0; t < 49; t++) s += b[lane*49 + t];
    s = rtf(s * (1.f/49.f));
    int seg = base + lane;
    g_xm[seg] = s;
    g_hA[TC*DD + seg] = s;
}

// ---------------- prep: zeros, pad+round base_w, round all weights ---------
__global__ void k_prep(const float* __restrict__ wq, const float* __restrict__ wk,
                       const float* __restrict__ gw, const float* __restrict__ bw) {
    int i = blockIdx.x*256 + threadIdx.x;
    if (i < DD*DD) {
        g_wR[i]           = rtf(wq[i]);
        g_wR[DD*DD + i]   = rtf(wk[i]);
        g_wR[2*DD*DD + i] = rtf(gw[i]);
        g_wR[3*DD*DD + i] = rtf(gw[DD*DD + i]);
    }
    if (i < NT*DD) g_tsum[i] = 0.f;
    if (i < NC*DD) g_csum[i] = 0.f;
    if (i < NT) g_cntT[i] = 0;
    if (i < NC) g_cntC[i] = 0;
    if (i < TC*DD) g_C69[i] = 0.f;
    if (i < DD*CFLD) {
        int r = i / CFLD, c = i - r*CFLD;
        g_bwPad[i] = (c < NC) ? rtf(bw[r*NC + c]) : 0.f;
    }
}
__global__ void k_count(const int* __restrict__ to, const int* __restrict__ lb) {
    int i = blockIdx.x*256 + threadIdx.x;
    if (i < BN) { atomicAdd(&g_cntT[to[i]], 1); atomicAdd(&g_cntC[lb[i]], 1); }
}
__global__ void k_segsum(const int* __restrict__ to, const int* __restrict__ lb) {
    __shared__ float sT[NT][64];
    __shared__ float sC[NC][64];
    int t = threadIdx.x;
    int cr = t & 63, rr = t >> 6;
    int r0 = blockIdx.y * 64, c0 = blockIdx.x * 64;
    for (int i = t; i < NT*64; i += 256) ((float*)sT)[i] = 0.f;
    for (int i = t; i < NC*64; i += 256) ((float*)sC)[i] = 0.f;
    __syncthreads();
    for (int r = r0 + rr; r < r0 + 64; r += 4) {
        int tt = to[r], cc = lb[r];
        float v = g_xm[r*DD + c0 + cr];
        atomicAdd(&sT[tt][cr], v);
        atomicAdd(&sC[cc][cr], v);
    }
    __syncthreads();
    for (int i = t; i < NT*64; i += 256)
        atomicAdd(&g_tsum[(i>>6)*DD + c0 + (i&63)], ((float*)sT)[i]);
    for (int i = t; i < NC*64; i += 256)
        atomicAdd(&g_csum[(i>>6)*DD + c0 + (i&63)], ((float*)sC)[i]);
}
__global__ void k_t1c1(const float* __restrict__ trep, const float* __restrict__ cpro) {
    int i = blockIdx.x*256 + threadIdx.x;
    if (i >= TC*DD) return;
    int seg = i / DD, d = i % DD;
    float v;
    if (seg < NT) {
        float cnt = fmaxf((float)g_cntT[seg], 1.f);
        v = 0.9f*trep[i] + 0.1f*g_tsum[i]/cnt;
    } else {
        int c = seg - NT;
        float cnt = fmaxf((float)g_cntC[c], 1.f);
        v = 0.9f*cpro[c*DD+d] + 0.1f*g_csum[c*DD+d]/cnt;
    }
    g_hA[i] = rtf(v);
}

// ---------------- graph kernels ----------------
__global__ void k_d2cross() {
    int c = blockIdx.x;
    int w = threadIdx.x >> 5, lane = threadIdx.x & 31;
    __shared__ float sd2[NT];
    const float* t1 = g_hA;
    const float* c1 = g_hA + NT*DD;
    float s = 0.f;
    for (int d = lane; d < DD; d += 32) {
        float df = t1[w*DD+d] - c1[c*DD+d];
        s += df*df;
    }
    #pragma unroll
    for (int o = 16; o; o >>= 1) s += __shfl_xor_sync(0xffffffffu, s, o);
    if (lane == 0) sd2[w] = s;
    __syncthreads();
    if (threadIdx.x == 0) {
        float l[NT], mx = -1e30f;
        for (int t = 0; t < NT; t++) { l[t] = -sd2[t]*(1.f/16.f); mx = fmaxf(mx, l[t]); }
        float Z = 0.f;
        for (int t = 0; t < NT; t++) { l[t] = expf(l[t]-mx); Z += l[t]; }
        for (int t = 0; t < NT; t++) {
            float p = l[t]/Z;
            g_cross[t*NC + c] = p;
            g_adj[t*TC + NT + c] = p;
            g_adj[(NT+c)*TC + t] = p;
        }
    }
}
__global__ void k_tg(const float* __restrict__ tw, const float* __restrict__ tb) {
    int i = blockIdx.x >> 2, j = blockIdx.x & 3;
    int lane = threadIdx.x;
    const float* t1 = g_hA;
    float s = 0.f;
    for (int d = lane; d < DD; d += 32)
        s += fabsf(t1[i*DD+d]-t1[j*DD+d]) * tw[d];
    #pragma unroll
    for (int o = 16; o; o >>= 1) s += __shfl_xor_sync(0xffffffffu, s, o);
    if (lane == 0) {
        float v = 1.f/(1.f+expf(-(s + tb[0])));
        if (i == j) v = 0.f;
        g_adj[i*TC+j] = v;
    }
}
__global__ void k_cg(const float* __restrict__ cw, const float* __restrict__ cb) {
    int i = blockIdx.x;
    int w = threadIdx.x >> 5, lane = threadIdx.x & 31;
    int j = blockIdx.y*4 + w;
    if (j >= NC) return;
    const float* c1 = g_hA + NT*DD;
    float s = 0.f;
    for (int d = lane; d < DD; d += 32)
        s += fabsf(c1[i*DD+d]-c1[j*DD+d]) * cw[d];
    #pragma unroll
    for (int o = 16; o; o >>= 1) s += __shfl_xor_sync(0xffffffffu, s, o);
    if (lane == 0) {
        float v = 1.f/(1.f+expf(-(s + cb[0])));
        if (i == j) v = 0.f;
        g_adj[(NT+i)*TC + NT+j] = v;
    }
}
__global__ void k_ae(float* out) {
    __shared__ float s[NC];
    int c = threadIdx.x;
    float a = 0.f;
    for (int t = 0; t < NT; t++) { float p = g_cross[t*NC+c]; a += p*logf(p); }
    s[c] = a;
    __syncthreads();
    if (c == 0) { float r = 0.f; for (int i = 0; i < NC; i++) r += s[i]; out[0] = r/(float)NC; }
}

// ---------------- tf32 GEMM (128x128 block tile, cp.async, no hot CVT) -----
#define GEMM_SMEM ((2*128*36 + 2*32*136)*4)
#define AS(p,r,c) smp[(p)*4608 + (r)*36 + (c)]
#define BS(p,r,c) smp[9216 + (p)*4352 + (r)*136 + (c)]
__global__ void __launch_bounds__(256, 2) k_gemm3(
        int aSel, int bSel, const float* __restrict__ Bp, int cSel,
        int M, int N, int K, int lda, int ldb, int ldc,
        const float* __restrict__ bias, int relu,
        const float* __restrict__ tcw, const int* __restrict__ to,
        float* yout) {
    extern __shared__ float smp[];
    int by = blockIdx.y;
    const float* A = selA3(aSel);
    const float* B = selB3(bSel, Bp);
    float* C = yout ? yout : selC3(cSel);
    int tid = threadIdx.x;
    int w = tid >> 5, lane = tid & 31, g = lane >> 2, t = lane & 3;
    int wm = (w & 3) * 32, wn = (w >> 2) * 64;
    int m0 = by*128, n0 = blockIdx.x*128;
    uint32_t sb = (uint32_t)__cvta_generic_to_shared(smp);

    auto fillA = [&](int p, int k0) {
        #pragma unroll
        for (int r = 0; r < 4; r++) {
            int idx = tid + 256*r;
            int row = idx >> 3, fc = idx & 7;
            int gm = m0 + row, gk = k0 + fc*4;
            int sz = 16;
            if (gm >= M) sz = 0;
            int rem = (K - gk)*4;
            if (rem < sz) sz = rem < 0 ? 0 : rem;
            const float* src = sz > 0 ? &A[(size_t)gm*lda + gk] : A;
            cpa16(sb + (uint32_t)(p*4608 + row*36 + fc*4)*4u, src, sz);
        }
    };
    auto fillB = [&](int p, int k0) {
        #pragma unroll
        for (int r = 0; r < 4; r++) {
            int idx = tid + 256*r;
            int row = idx >> 5, c4 = (idx & 31)*4;
            int gk = k0 + row, gn = n0 + c4;
            int sz = 16;
            if (gk >= K) sz = 0;
            int rem = (N - gn)*4;
            if (rem < sz) sz = rem < 0 ? 0 : rem;
            const float* src = sz > 0 ? &B[(size_t)gk*ldb + gn] : B;
            cpa16(sb + (uint32_t)(9216 + p*4352 + row*136 + c4)*4u, src, sz);
        }
    };

    float acc[2][8][4] = {};
    int nk = (K + 31) >> 5;
    fillA(0, 0); fillB(0, 0); CPA_COMMIT();
    for (int kc = 0; kc < nk; kc++) {
        CPA_WAIT0();
        __syncthreads();
        if (kc + 1 < nk) { fillA((kc+1)&1, (kc+1)*32); fillB((kc+1)&1, (kc+1)*32); CPA_COMMIT(); }
        int p = kc & 1;
        #pragma unroll
        for (int kk = 0; kk < 32; kk += 8) {
            uint32_t a[2][4];
            #pragma unroll
            for (int mi = 0; mi < 2; mi++) {
                a[mi][0] = __float_as_uint(AS(p, wm+mi*16+g  , kk+t));
                a[mi][1] = __float_as_uint(AS(p, wm+mi*16+g+8, kk+t));
                a[mi][2] = __float_as_uint(AS(p, wm+mi*16+g  , kk+t+4));
                a[mi][3] = __float_as_uint(AS(p, wm+mi*16+g+8, kk+t+4));
            }
            uint32_t b[8][2];
            #pragma unroll
            for (int ni = 0; ni < 8; ni++) {
                b[ni][0] = __float_as_uint(BS(p, kk+t  , wn+ni*8+g));
                b[ni][1] = __float_as_uint(BS(p, kk+t+4, wn+ni*8+g));
            }
            #pragma unroll
            for (int mi = 0; mi < 2; mi++)
                #pragma unroll
                for (int ni = 0; ni < 8; ni++)
                    mma8(acc[mi][ni], a[mi][0], a[mi][1], a[mi][2], a[mi][3],
                         b[ni][0], b[ni][1]);
        }
    }
    #pragma unroll
    for (int mi = 0; mi < 2; mi++) {
        int r0 = m0 + wm + mi*16 + g, r1 = r0 + 8;
        #pragma unroll
        for (int ni = 0; ni < 8; ni++) {
            int n = n0 + wn + ni*8 + 2*t;
            float bv0 = 0.f, bv1 = 0.f;
            if (bias) { if (n < N) bv0 = bias[n]; if (n+1 < N) bv1 = bias[n+1]; }
            float v00 = acc[mi][ni][0] + bv0, v01 = acc[mi][ni][1] + bv1;
            float v10 = acc[mi][ni][2] + bv0, v11 = acc[mi][ni][3] + bv1;
            if (relu) {
                v00 = fmaxf(v00, 0.f); v01 = fmaxf(v01, 0.f);
                v10 = fmaxf(v10, 0.f); v11 = fmaxf(v11, 0.f);
            }
            if (yout) {
                if (r0 < M) {
                    if (n < N)   C[(size_t)r0*ldc + n]   = tcw[to[r0]*NC + n]   * v00;
                    if (n+1 < N) C[(size_t)r0*ldc + n+1] = tcw[to[r0]*NC + n+1] * v01;
                }
                if (r1 < M) {
                    if (n < N)   C[(size_t)r1*ldc + n]   = tcw[to[r1]*NC + n]   * v10;
                    if (n+1 < N) C[(size_t)r1*ldc + n+1] = tcw[to[r1]*NC + n+1] * v11;
                }
            } else {
                v00 = rtf(v00); v01 = rtf(v01); v10 = rtf(v10); v11 = rtf(v11);
                if (r0 < M) {
                    if (n < N)   C[(size_t)r0*ldc + n]   = v00;
                    if (n+1 < N) C[(size_t)r0*ldc + n+1] = v01;
                }
                if (r1 < M) {
                    if (n < N)   C[(size_t)r1*ldc + n]   = v10;
                    if (n+1 < N) C[(size_t)r1*ldc + n+1] = v11;
                }
            }
        }
    }
}

// ---------------- attention (cp.async, streaming softmax, raw loads) -------
// split = blockIdx.y + splitBase. Split 0 covers jt 0 ONLY (tc keys + first
// x-keys, writes l69); splits 1..8 cover jt 1..32 (x-keys only, 4 each).
#define ATTN_SMEM ((2*128*36*2)*4)
#define QS(p,r,c) smp[(p)*4608 + (r)*36 + (c)]
#define KS(p,r,c) smp[9216 + (p)*4608 + (r)*36 + (c)]
__global__ void __launch_bounds__(256, 2) k_attn3(int splitBase) {
    extern __shared__ float smp[];
    __shared__ float sm_m[2][128];
    __shared__ float sm_z[2][128];
    int tid = threadIdx.x;
    int w = tid >> 5, lane = tid & 31, g = lane >> 2, t = lane & 3;
    int wm = (w & 3) * 32, wn = (w >> 2) * 64;
    int half = w >> 2;
    int i0 = blockIdx.x*128;
    int split = blockIdx.y + splitBase;
    const float sc = 0.044194173824159216f;   // 1/sqrt(512)
    uint32_t sb = (uint32_t)__cvta_generic_to_shared(smp);

    auto fillQ = [&](int p, int k0) {
        #pragma unroll
        for (int r = 0; r < 4; r++) {
            int idx = tid + 256*r;
            int row = idx >> 3, fc = idx & 7;
            cpa16(sb + (uint32_t)(p*4608 + row*36 + fc*4)*4u,
                  &g_q[(size_t)(i0+row)*DD + k0 + fc*4], 16);
        }
    };
    auto fillK = [&](int p, int j0v, int k0) {
        #pragma unroll
        for (int r = 0; r < 4; r++) {
            int idx = tid + 256*r;
            int row = idx >> 3, fc = idx & 7;
            int gj = j0v + row;
            int sz = gj < NS ? 16 : 0;
            const float* src = sz ? &g_kall[(size_t)gj*DD + k0 + fc*4] : g_kall;
            cpa16(sb + (uint32_t)(9216 + p*4608 + row*36 + fc*4)*4u, src, sz);
        }
    };

    float mr[2][2] = {{-1e30f,-1e30f},{-1e30f,-1e30f}};
    float zr[2][2] = {{0.f,0.f},{0.f,0.f}};
    int jt0, jt1;
    if (split == 0) { jt0 = 0; jt1 = 1; }
    else {
        jt0 = 1 + (split - 1)*JPT;
        jt1 = jt0 + JPT; if (jt1 > NJT) jt1 = NJT;
    }
    int cg = 0;
    fillQ(0, 0); fillK(0, jt0*128, 0); CPA_COMMIT();
    for (int jt = jt0; jt < jt1; jt++) {
        int j0 = jt*128;
        float acc[2][8][4] = {};
        for (int c = 0; c < 16; c++, cg++) {
            CPA_WAIT0();
            __syncthreads();
            int p = cg & 1;
            if (c < 15) {
                fillQ(p^1, (c+1)*32); fillK(p^1, j0, (c+1)*32); CPA_COMMIT();
            } else if (jt + 1 < jt1) {
                fillQ(p^1, 0); fillK(p^1, (jt+1)*128, 0); CPA_COMMIT();
            }
            #pragma unroll
            for (int kk = 0; kk < 32; kk += 8) {
                uint32_t a[2][4];
                #pragma unroll
                for (int mi = 0; mi < 2; mi++) {
                    a[mi][0] = __float_as_uint(QS(p, wm+mi*16+g  , kk+t));
                    a[mi][1] = __float_as_uint(QS(p, wm+mi*16+g+8, kk+t));
                    a[mi][2] = __float_as_uint(QS(p, wm+mi*16+g  , kk+t+4));
                    a[mi][3] = __float_as_uint(QS(p, wm+mi*16+g+8, kk+t+4));
                }
                uint32_t b[8][2];
                #pragma unroll
                for (int ni = 0; ni < 8; ni++) {
                    b[ni][0] = __float_as_uint(KS(p, wn+ni*8+g, kk+t));
                    b[ni][1] = __float_as_uint(KS(p, wn+ni*8+g, kk+t+4));
                }
                #pragma unroll
                for (int mi = 0; mi < 2; mi++)
                    #pragma unroll
                    for (int ni = 0; ni < 8; ni++)
                        mma8(acc[mi][ni], a[mi][0], a[mi][1], a[mi][2], a[mi][3],
                             b[ni][0], b[ni][1]);
            }
        }
        int doL = (split == 0 && jt == 0);
        #pragma unroll
        for (int mi = 0; mi < 2; mi++) {
            int r0g = i0 + wm + mi*16 + g, r1g = r0g + 8;
            float lm0 = -1e30f, lm1 = -1e30f;
            #pragma unroll
            for (int ni = 0; ni < 8; ni++) {
                int base = j0 + wn + ni*8 + 2*t;
                float v0 = (base   < NS) ? acc[mi][ni][0]*sc : -1e30f;
                float v1 = (base+1 < NS) ? acc[mi][ni][1]*sc : -1e30f;
                float v2 = (base   < NS) ? acc[mi][ni][2]*sc : -1e30f;
                float v3 = (base+1 < NS) ? acc[mi][ni][3]*sc : -1e30f;
                acc[mi][ni][0] = v0; acc[mi][ni][1] = v1;
                acc[mi][ni][2] = v2; acc[mi][ni][3] = v3;
                if (doL) {
                    int c0 = wn + ni*8 + 2*t;
                    if (c0 < TC) {
                        g_l69[(size_t)r0g*TC + c0] = v0;
                        g_l69[(size_t)r1g*TC + c0] = v2;
                    }
                    if (c0 + 1 < TC) {
                        g_l69[(size_t)r0g*TC + c0+1] = v1;
                        g_l69[(size_t)r1g*TC + c0+1] = v3;
                    }
                }
                lm0 = fmaxf(lm0, fmaxf(v0, v1));
                lm1 = fmaxf(lm1, fmaxf(v2, v3));
            }
            lm0 = fmaxf(lm0, __shfl_xor_sync(0xffffffffu, lm0, 1));
            lm0 = fmaxf(lm0, __shfl_xor_sync(0xffffffffu, lm0, 2));
            lm1 = fmaxf(lm1, __shfl_xor_sync(0xffffffffu, lm1, 1));
            lm1 = fmaxf(lm1, __shfl_xor_sync(0xffffffffu, lm1, 2));
            float nm0 = fmaxf(mr[mi][0], lm0), nm1 = fmaxf(mr[mi][1], lm1);
            float p0 = 0.f, p1 = 0.f;
            #pragma unroll
            for (int ni = 0; ni < 8; ni++) {
                p0 += __expf(acc[mi][ni][0]-nm0) + __expf(acc[mi][ni][1]-nm0);
                p1 += __expf(acc[mi][ni][2]-nm1) + __expf(acc[mi][ni][3]-nm1);
            }
            p0 += __shfl_xor_sync(0xffffffffu, p0, 1);
            p0 += __shfl_xor_sync(0xffffffffu, p0, 2);
            p1 += __shfl_xor_sync(0xffffffffu, p1, 1);
            p1 += __shfl_xor_sync(0xffffffffu, p1, 2);
            zr[mi][0] = zr[mi][0]*__expf(mr[mi][0] - nm0) + p0; mr[mi][0] = nm0;
            zr[mi][1] = zr[mi][1]*__expf(mr[mi][1] - nm1) + p1; mr[mi][1] = nm1;
        }
    }
    if (t == 0) {
        #pragma unroll
        for (int mi = 0; mi < 2; mi++) {
            int r = wm + mi*16 + g;
            sm_m[half][r]     = mr[mi][0];  sm_z[half][r]     = zr[mi][0];
            sm_m[half][r + 8] = mr[mi][1];  sm_z[half][r + 8] = zr[mi][1];
        }
    }
    __syncthreads();
    if (tid < 128) {
        float m0 = sm_m[0][tid], m1 = sm_m[1][tid];
        float m = fmaxf(m0, m1);
        float z = sm_z[0][tid]*__expf(m0 - m) + sm_z[1][tid]*__expf(m1 - m);
        g_mp[split*BN + i0 + tid] = m;
        g_zp[split*BN + i0 + tid] = z;
    }
}

// ---------------- combine splits + first-69 softmax -> cf (tf32) ----------
__global__ void k_cf() {
    int i = blockIdx.x;
    int j = threadIdx.x;
    __shared__ float sh[2];
    if (j == 0) {
        float m = -1e30f;
        #pragma unroll
        for (int s = 0; s < NSPL; s++) m = fmaxf(m, g_mp[s*BN + i]);
        float z = 0.f;
        #pragma unroll
        for (int s = 0; s < NSPL; s++) z += g_zp[s*BN + i]*__expf(g_mp[s*BN + i] - m);
        sh[0] = m; sh[1] = 1.f/z;
    }
    __syncthreads();
    if (j < CFLD)
        g_cf[i*CFLD + j] = (j < TC) ? rtf(__expf(g_l69[i*TC + j] - sh[0]) * sh[1]) : 0.f;
}

// ---------------- GNN tc-rows partial: C69 += cf^T @ hw_x ----------------
__global__ void k_outtc() {
    __shared__ float cfs[64][72];
    __shared__ float hws[64][64];
    int t = threadIdx.x, tx = t & 63, ty = t >> 6;
    int n0 = blockIdx.x*64;
    int b0 = blockIdx.y*256;
    float acc[18];
    #pragma unroll
    for (int k = 0; k < 18; k++) acc[k] = 0.f;
    for (int bc = 0; bc < 256; bc += 64) {
        int bb = b0 + bc;
        for (int i = t; i < 64*TC; i += 256) {
            int r = i/TC, k = i%TC;
            cfs[r][k] = g_cf[(size_t)(bb+r)*CFLD + k];
        }
        for (int i = t; i < 64*64; i += 256) {
            int r = i >> 6, n = i & 63;
            hws[r][n] = g_hw[(size_t)(TC+bb+r)*DD + n0 + n];
        }
        __syncthreads();
        for (int r = 0; r < 64; r++) {
            float hv = hws[r][tx];
            #pragma unroll
            for (int k = 0; k < 18; k++) {
                int m = ty + 4*k;
                if (m < TC) acc[k] += cfs[r][m]*hv;
            }
        }
        __syncthreads();
    }
    #pragma unroll
    for (int k = 0; k < 18; k++) {
        int m = ty + 4*k;
        if (m < TC) atomicAdd(&g_C69[m*DD + n0 + tx], acc[k]);
    }
}

// ---------------- finalize tc rows (layer 0), tf32-rounded ------------
__global__ void k_fintc(const float* __restrict__ gb) {
    int m = blockIdx.x;      // 69
    int n = threadIdx.x;     // 512
    float v = g_C69[m*DD + n];
    for (int j = 0; j < TC; j++)
        v += g_adj[m*TC+j] * g_hw[j*DD + n];
    v += gb[n];
    g_hB[m*DD + n] = rtf(fmaxf(v, 0.f));
}

// ---------------- labels ----------------
__global__ void k_labels(const int* __restrict__ lb, float* out, int off, int out_size) {
    int i = blockIdx.x*256 + threadIdx.x;
    if (i < BN && off + i < out_size) out[off + i] = (float)lb[i];
}

// ======================== host ========================
extern "C" void kernel_launch(void* const* d_in, const int* in_sizes, int n_in,
                              void* d_out, int out_size) {
    const float* x    = (const float*)d_in[0];
    const int*   lb   = (const int*)d_in[1];
    const int*   to   = (const int*)d_in[2];
    const float* trep = (const float*)d_in[3];
    const float* cpro = (const float*)d_in[4];
    const float* tw   = (const float*)d_in[5];
    const float* tb   = (const float*)d_in[6];
    const float* cw   = (const float*)d_in[7];
    const float* cb   = (const float*)d_in[8];
    const float* wq   = (const float*)d_in[9];
    const float* wk   = (const float*)d_in[10];
    const float* gw   = (const float*)d_in[11];
    const float* gb   = (const float*)d_in[12];
    const float* bw   = (const float*)d_in[13];
    const float* bb   = (const float*)d_in[14];
    const float* tcw  = (const float*)d_in[15];
    float* out = (float*)d_out;

    cudaFuncSetAttribute(k_gemm3, cudaFuncAttributeMaxDynamicSharedMemorySize, GEMM_SMEM);
    cudaFuncSetAttribute(k_attn3, cudaFuncAttributeMaxDynamicSharedMemorySize, ATTN_SMEM);

    float* wRp = nullptr;
    cudaGetSymbolAddress((void**)&wRp, g_wR);
    const float* wqR  = wRp;
    const float* wkR  = wRp + DD*DD;
    const float* gw1R = wRp + 2*DD*DD;
    const float* gw2R = wRp + 3*DD*DD;

    int y_off = (out_size > BN*NC) ? 1 : 0;
    int lbl_off = y_off + BN*NC;

    // FORK (capture-legal side-stream entry)
    cudaEventRecord(g_eF, 0);
    cudaStreamWaitEvent(g_s1, g_eF, 0);
    // side: prep + count, concurrent with xm
    k_prep<<<(DD*DD + 255)/256, 256, 0, g_s1>>>(wq, wk, gw, bw);
    k_count<<<16, 256, 0, g_s1>>>(to, lb);
    cudaEventRecord(g_e0, g_s1);
    // main: xm
    k_xm<<<16384, 128>>>(x);
    cudaEventRecord(g_e1, 0);
    // side: q = xm@wqR (needs xm + prep), concurrent with kall_x on main
    cudaStreamWaitEvent(g_s1, g_e1, 0);
    k_gemm3<<<dim3(4, 32), 256, GEMM_SMEM, g_s1>>>(0, 0, wqR, 0, BN, DD, DD, DD, DD, DD,
                                                   nullptr, 0, nullptr, nullptr, nullptr);
    cudaEventRecord(g_e4, g_s1);
    // main: kall_x = xm@wkR -> g_kall rows 69.. (needs xm + prep)
    cudaStreamWaitEvent(0, g_e0, 0);
    k_gemm3<<<dim3(4, 32), 256, GEMM_SMEM>>>(0, 0, wkR, 6, BN, DD, DD, DD, DD, DD,
                                             nullptr, 0, nullptr, nullptr, nullptr);
    // main: attention splits 1..8 (jt 1..32, x-keys only; needs q + kall_x)
    cudaStreamWaitEvent(0, g_e4, 0);
    k_attn3<<<dim3(32, 8), 256, ATTN_SMEM>>>(1);
    // side (hidden under attnA): segsum -> t1c1 -> kall_tc -> graphs -> hw
    k_segsum<<<dim3(8, 64), 256, 0, g_s1>>>(to, lb);
    k_t1c1<<<(TC*DD + 255)/256, 256, 0, g_s1>>>(trep, cpro);
    k_gemm3<<<dim3(4, 1), 256, GEMM_SMEM, g_s1>>>(1, 0, wkR, 1, TC, DD, DD, DD, DD, DD,
                                                  nullptr, 0, nullptr, nullptr, nullptr);
    cudaEventRecord(g_e5, g_s1);   // kall_tc ready
    k_d2cross<<<65, 128, 0, g_s1>>>();
    k_tg<<<16, 32, 0, g_s1>>>(tw, tb);
    k_cg<<<dim3(65, 17), 128, 0, g_s1>>>(cw, cb);
    if (y_off) k_ae<<<1, 65, 0, g_s1>>>(out);
    k_gemm3<<<dim3(4, 33), 256, GEMM_SMEM, g_s1>>>(1, 0, gw1R, 2, NS, DD, DD, DD, DD, DD,
                                                   nullptr, 0, nullptr, nullptr, nullptr);
    cudaEventRecord(g_e6, g_s1);   // hw + graphs ready
    // main: attention split 0 (jt 0 only, ~1/33 of work; needs kall_tc)
    cudaStreamWaitEvent(0, g_e5, 0);
    k_attn3<<<dim3(32, 1), 256, ATTN_SMEM>>>(0);
    k_cf<<<4096, 96>>>();
    // main tail (needs hw + adj): outtc -> fintc -> hw2 -> L1x -> y
    cudaStreamWaitEvent(0, g_e6, 0);
    k_outtc<<<dim3(8, 16), 256>>>();
    k_fintc<<<69, 512>>>(gb);
    k_gemm3<<<dim3(4, 1), 256, GEMM_SMEM>>>(2, 0, gw2R, 5, TC, DD, DD, DD, DD, DD,
                                            nullptr, 0, nullptr, nullptr, nullptr);
    k_gemm3<<<dim3(4, 32), 256, GEMM_SMEM>>>(3, 3, nullptr, 4, BN, DD, CFLD, CFLD, DD, DD,
                                             gb + DD, 1, nullptr, nullptr, nullptr);
    k_gemm3<<<dim3(1, 32), 256, GEMM_SMEM>>>(4, 2, nullptr, 0, BN, NC, DD, DD, CFLD, NC,
                                             bb, 0, tcw, to, out + y_off);
    k_labels<<<16, 256>>>(lb, out, lbl_off, out_size);
}